// round 9
// baseline (speedup 1.0000x reference)
#include <cuda_runtime.h>
#include <cstdint>

// Problem constants (fixed by reference)
#define BB      4
#define HW      400
#define OUTD    100
#define STRIDEV 4
#define NPTS    10000          // OUTD*OUTD
#define NSPLIT  4              // source-dimension split
#define MSLICE  (NPTS/NSPLIT)  // 2500 sources per split
#define TCHUNK  128            // threads per block == targets per block

// Tile: 250 source-pair groups = 500 sources = 500 float4 = 8 KB smem
#define TILE_GROUPS 250
#define TILE_F4     (TILE_GROUPS * 2)
#define NTILES      (MSLICE / (TILE_GROUPS * 2))   // 2500/500 = 5

// Scratch (device globals; no allocation allowed)
__device__ float4 g_t4[BB * NPTS];            // (-2x,-2y,-2z, |t|^2)
// Pair-packed sources: per group p (sources 2p,2p+1), 8 floats:
//   [x0,x1, y0,y1, z0,z1, w0,w1]  (w = |s|^2)
__device__ float  g_sp[BB * NPTS * 4];
__device__ float  g_part[BB * NSPLIT * NPTS];

// ---------------------------------------------------------------------------
// Phase 0: downsample + pack.
// ---------------------------------------------------------------------------
__global__ void pack_kernel(const float* __restrict__ tp,
                            const float* __restrict__ sp) {
    int idx = blockIdx.x * blockDim.x + threadIdx.x;
    if (idx >= 2 * BB * NPTS) return;
    bool is_src = idx >= BB * NPTS;
    int lid = is_src ? idx - BB * NPTS : idx;
    int b = lid / NPTS;
    int n = lid - b * NPTS;
    int oh = n / OUTD;
    int ow = n - oh * OUTD;
    const float* p = is_src ? sp : tp;
    long base = (long)b * 3 * HW * HW + (long)(oh * STRIDEV) * HW + (ow * STRIDEV);
    float x = p[base];
    float y = p[base + HW * HW];
    float z = p[base + 2 * HW * HW];
    float sq = x * x + y * y + z * z;
    if (is_src) {
        int pgrp = n >> 1;
        int h = n & 1;
        float* dst = g_sp + (size_t)(b * (NPTS / 2) + pgrp) * 8;
        dst[0 + h] = x;
        dst[2 + h] = y;
        dst[4 + h] = z;
        dst[6 + h] = sq;
    } else {
        g_t4[lid] = make_float4(-2.0f * x, -2.0f * y, -2.0f * z, sq);
    }
}

// ---------------------------------------------------------------------------
// Phase 1: brute-force partial min using packed f32x2 FMA.
// Per source-pair group: 2x LDS.128 (as ld.shared.v2.b64), 3x fma.rn.f32x2,
// 2x FMNMX.  grid = (ceil(NPTS/TCHUNK), NSPLIT, BB), block = TCHUNK.
// ---------------------------------------------------------------------------

// One group: v01 = w01 + tz2*z01 + ty2*y01 + tx2*x01 (two sources at once)
#define GROUP(OFF)                                                         \
    do {                                                                   \
        float v0, v1;                                                      \
        asm volatile(                                                      \
            "{\n\t"                                                        \
            ".reg .b64 xa, ya, za, wa, v;\n\t"                             \
            "ld.shared.v2.b64 {xa, ya}, [%2+%3];\n\t"                      \
            "ld.shared.v2.b64 {za, wa}, [%2+%4];\n\t"                      \
            "fma.rn.f32x2 v, %7, za, wa;\n\t"                              \
            "fma.rn.f32x2 v, %6, ya, v;\n\t"                               \
            "fma.rn.f32x2 v, %5, xa, v;\n\t"                               \
            "mov.b64 {%0, %1}, v;\n\t"                                     \
            "}"                                                            \
            : "=f"(v0), "=f"(v1)                                           \
            : "r"(addr), "n"(OFF), "n"((OFF) + 16),                        \
              "l"(tx2), "l"(ty2), "l"(tz2));                               \
        best0 = fminf(best0, v0);                                          \
        best1 = fminf(best1, v1);                                          \
    } while (0)

__global__ void __launch_bounds__(TCHUNK)
dist_kernel() {
    __shared__ float4 tile[TILE_F4];

    int n     = blockIdx.x * TCHUNK + threadIdx.x;
    int split = blockIdx.y;
    int b     = blockIdx.z;

    float4 t = g_t4[b * NPTS + (n < NPTS ? n : 0)];

    // Duplicate target components into packed f32x2 registers (once).
    unsigned long long tx2, ty2, tz2;
    asm("mov.b64 %0, {%1, %1};" : "=l"(tx2) : "f"(t.x));
    asm("mov.b64 %0, {%1, %1};" : "=l"(ty2) : "f"(t.y));
    asm("mov.b64 %0, {%1, %1};" : "=l"(tz2) : "f"(t.z));

    float best0 = 3.4e38f, best1 = 3.4e38f;

    // Pair-packed source slice for (b, split): groups [split*1250, ...)
    const float4* __restrict__ src =
        (const float4*)g_sp + (size_t)(b * (NPTS / 2) + split * (MSLICE / 2)) * 2;

    uint32_t sbase = (uint32_t)__cvta_generic_to_shared(tile);

    for (int tb = 0; tb < NTILES; ++tb) {
        __syncthreads();
        const float4* gsrc = src + tb * TILE_F4;
        #pragma unroll
        for (int j = threadIdx.x; j < TILE_F4; j += TCHUNK)
            tile[j] = gsrc[j];
        __syncthreads();

        uint32_t addr = sbase;
        for (int it = 0; it < TILE_GROUPS / 10; ++it) {
            GROUP(0);   GROUP(32);  GROUP(64);  GROUP(96);  GROUP(128);
            GROUP(160); GROUP(192); GROUP(224); GROUP(256); GROUP(288);
            addr += 320;
        }
    }

    if (n < NPTS)
        g_part[(b * NSPLIT + split) * NPTS + n] = fminf(best0, best1);
}

// ---------------------------------------------------------------------------
// Phase 2 (fused): combine splits, add |t|^2, deterministic tree reduce,
// final scale. Single global sum == mean of per-batch means (equal sizes).
// grid = 1, block = 512.
// ---------------------------------------------------------------------------
__global__ void reduce_final_kernel(float* __restrict__ out) {
    __shared__ float ssum[512];
    float acc = 0.0f;
    for (int i = threadIdx.x; i < BB * NPTS; i += 512) {
        int b = i / NPTS;
        int n = i - b * NPTS;
        float m = g_part[(b * NSPLIT + 0) * NPTS + n];
        #pragma unroll
        for (int s = 1; s < NSPLIT; ++s)
            m = fminf(m, g_part[(b * NSPLIT + s) * NPTS + n]);
        acc += m + g_t4[b * NPTS + n].w;
    }
    ssum[threadIdx.x] = acc;
    __syncthreads();
    for (int ofs = 256; ofs > 0; ofs >>= 1) {
        if (threadIdx.x < ofs) ssum[threadIdx.x] += ssum[threadIdx.x + ofs];
        __syncthreads();
    }
    if (threadIdx.x == 0)
        out[0] = ssum[0] * (1.0f / (float)(BB * NPTS * 3));
}

extern "C" void kernel_launch(void* const* d_in, const int* in_sizes, int n_in,
                              void* d_out, int out_size) {
    const float* tp = (const float*)d_in[0];
    const float* sp = (const float*)d_in[1];
    float* out = (float*)d_out;

    int pack_threads = 2 * BB * NPTS;
    pack_kernel<<<(pack_threads + 255) / 256, 256>>>(tp, sp);

    dim3 grid((NPTS + TCHUNK - 1) / TCHUNK, NSPLIT, BB);
    dist_kernel<<<grid, TCHUNK>>>();

    reduce_final_kernel<<<1, 512>>>(out);
}

// round 10
// speedup vs baseline: 1.2186x; 1.2186x over previous
#include <cuda_runtime.h>
#include <cstdint>

// Problem constants (fixed by reference)
#define BB      4
#define HW      400
#define OUTD    100
#define STRIDEV 4
#define NPTS    10000            // OUTD*OUTD
#define NSPLIT  8                // source-dimension split
#define MSLICE  (NPTS/NSPLIT)    // 1250 sources per split
#define TPB     128              // threads per block
#define TGTBLK  (2*TPB)          // 256 targets per block (2 per thread)
#define GX      ((NPTS + TGTBLK - 1) / TGTBLK)   // 40

// Scratch (device globals; no allocation allowed)
__device__ float4 g_t4[BB * NPTS];            // (-2x,-2y,-2z, |t|^2)
__device__ float4 g_s4[BB * NPTS];            // ( x,  y,  z, |s|^2)
__device__ float  g_part[BB * NSPLIT * NPTS];

// ---------------------------------------------------------------------------
// Phase 0: downsample + pack. idx < BB*NPTS -> target, else source.
// ---------------------------------------------------------------------------
__global__ void pack_kernel(const float* __restrict__ tp,
                            const float* __restrict__ sp) {
    int idx = blockIdx.x * blockDim.x + threadIdx.x;
    if (idx >= 2 * BB * NPTS) return;
    bool is_src = idx >= BB * NPTS;
    int lid = is_src ? idx - BB * NPTS : idx;
    int b = lid / NPTS;
    int n = lid - b * NPTS;
    int oh = n / OUTD;
    int ow = n - oh * OUTD;
    const float* p = is_src ? sp : tp;
    long base = (long)b * 3 * HW * HW + (long)(oh * STRIDEV) * HW + (ow * STRIDEV);
    float x = p[base];
    float y = p[base + HW * HW];
    float z = p[base + 2 * HW * HW];
    float sq = x * x + y * y + z * z;
    if (is_src) {
        g_s4[lid] = make_float4(x, y, z, sq);
    } else {
        g_t4[lid] = make_float4(-2.0f * x, -2.0f * y, -2.0f * z, sq);
    }
}

// ---------------------------------------------------------------------------
// Phase 1: brute-force partial min. 2 targets/thread, whole slice resident
// in smem (20 KB), zero barriers in the mainloop.
// grid = (GX, NSPLIT, BB), block = TPB.
// Per 2 sources: 2 LDS.128 + 12 FFMA + 4 FMNMX  (fma-pipe bound).
// ---------------------------------------------------------------------------
__global__ void __launch_bounds__(TPB)
dist_kernel() {
    __shared__ float4 tile[MSLICE];           // 1250 * 16B = 20 KB

    int n0    = blockIdx.x * TGTBLK + threadIdx.x;     // target A
    int n1    = n0 + TPB;                              // target B
    int split = blockIdx.y;
    int b     = blockIdx.z;

    int c0 = n0 < NPTS ? n0 : NPTS - 1;
    int c1 = n1 < NPTS ? n1 : NPTS - 1;
    float4 t0 = g_t4[b * NPTS + c0];
    float4 t1 = g_t4[b * NPTS + c1];

    // Load the whole source slice once.
    const float4* __restrict__ src = g_s4 + b * NPTS + split * MSLICE;
    #pragma unroll
    for (int j = threadIdx.x; j < MSLICE; j += TPB)
        tile[j] = src[j];
    __syncthreads();

    float b00 = 3.4e38f, b01 = 3.4e38f;   // target A accumulators
    float b10 = 3.4e38f, b11 = 3.4e38f;   // target B accumulators

    #pragma unroll 5
    for (int j = 0; j < MSLICE; j += 2) {
        float4 s0 = tile[j];
        float4 s1 = tile[j + 1];

        float v00 = fmaf(t0.x, s0.x, fmaf(t0.y, s0.y, fmaf(t0.z, s0.z, s0.w)));
        float v10 = fmaf(t1.x, s0.x, fmaf(t1.y, s0.y, fmaf(t1.z, s0.z, s0.w)));
        float v01 = fmaf(t0.x, s1.x, fmaf(t0.y, s1.y, fmaf(t0.z, s1.z, s1.w)));
        float v11 = fmaf(t1.x, s1.x, fmaf(t1.y, s1.y, fmaf(t1.z, s1.z, s1.w)));

        b00 = fminf(b00, v00);
        b10 = fminf(b10, v10);
        b01 = fminf(b01, v01);
        b11 = fminf(b11, v11);
    }

    float* part = g_part + (b * NSPLIT + split) * NPTS;
    if (n0 < NPTS) part[n0] = fminf(b00, b01);
    if (n1 < NPTS) part[n1] = fminf(b10, b11);
}

// ---------------------------------------------------------------------------
// Phase 2 (fused): combine splits, add |t|^2, deterministic tree reduce,
// final scale. Single global sum == mean of per-batch means (equal sizes).
// grid = 1, block = 512.
// ---------------------------------------------------------------------------
__global__ void reduce_final_kernel(float* __restrict__ out) {
    __shared__ float ssum[512];
    float acc = 0.0f;
    for (int i = threadIdx.x; i < BB * NPTS; i += 512) {
        int b = i / NPTS;
        int n = i - b * NPTS;
        float m = g_part[(b * NSPLIT + 0) * NPTS + n];
        #pragma unroll
        for (int s = 1; s < NSPLIT; ++s)
            m = fminf(m, g_part[(b * NSPLIT + s) * NPTS + n]);
        acc += m + g_t4[b * NPTS + n].w;
    }
    ssum[threadIdx.x] = acc;
    __syncthreads();
    for (int ofs = 256; ofs > 0; ofs >>= 1) {
        if (threadIdx.x < ofs) ssum[threadIdx.x] += ssum[threadIdx.x + ofs];
        __syncthreads();
    }
    if (threadIdx.x == 0)
        out[0] = ssum[0] * (1.0f / (float)(BB * NPTS * 3));
}

extern "C" void kernel_launch(void* const* d_in, const int* in_sizes, int n_in,
                              void* d_out, int out_size) {
    const float* tp = (const float*)d_in[0];
    const float* sp = (const float*)d_in[1];
    float* out = (float*)d_out;

    int pack_threads = 2 * BB * NPTS;
    pack_kernel<<<(pack_threads + 255) / 256, 256>>>(tp, sp);

    dim3 grid(GX, NSPLIT, BB);
    dist_kernel<<<grid, TPB>>>();

    reduce_final_kernel<<<1, 512>>>(out);
}